// round 14
// baseline (speedup 1.0000x reference)
#include <cuda_runtime.h>
#include <cuda_fp16.h>
#include <cstdint>

// Problem constants: E=8, N=512(K1), H=1024, P=512, F=100, B=128
#define E_NUM    8
#define B_TRIALS 128
#define F_BINS   100
#define N_IN     512
#define H_MID    1024
#define P_OUT    512
#define TOTAL_ROWS (B_TRIALS * F_BINS)   // 12800 packed rows
#define ACT_ROWS   13056                  // padded
#define MAXT128  120
#define MAXT64   224

// ---------------- device scratch ----------------
__device__ __half g_x[(size_t)TOTAL_ROWS * N_IN];
__device__ __half g_w1[(size_t)E_NUM * H_MID * N_IN];   // [E, N(out), K] K-major fp16
__device__ __half g_w2[(size_t)E_NUM * P_OUT * H_MID];
__device__ __half g_a[(size_t)ACT_ROWS * H_MID];        // act fp16, packed

__device__ int  g_order[B_TRIALS];
__device__ int  g_rowmap[TOTAL_ROWS];
__device__ int4 g_t128[MAXT128];
__device__ int  g_n128;
__device__ int4 g_t64[MAXT64];
__device__ int  g_n64;

// ---------------- low-level helpers ----------------
__device__ __forceinline__ uint32_t smem_to_u32(const void* p) {
    uint32_t a;
    asm("{ .reg .u64 t; cvta.to.shared.u64 t, %1; cvt.u32.u64 %0, t; }"
        : "=r"(a) : "l"(p));
    return a;
}
#define SWZ128(o) ((o) ^ (((o) >> 3) & 0x70))

__device__ __forceinline__ void cp16(uint32_t dst, const void* src) {
    asm volatile("cp.async.cg.shared.global [%0], [%1], 16;"
                 :: "r"(dst), "l"(src) : "memory");
}
#define CP_COMMIT() asm volatile("cp.async.commit_group;" ::: "memory")
#define CP_WAIT1()  asm volatile("cp.async.wait_group 1;" ::: "memory")

__device__ __forceinline__ void ldsm4(uint32_t* r, uint32_t addr) {
    asm volatile("ldmatrix.sync.aligned.m8n8.x4.shared.b16 {%0,%1,%2,%3}, [%4];"
                 : "=r"(r[0]), "=r"(r[1]), "=r"(r[2]), "=r"(r[3]) : "r"(addr));
}
__device__ __forceinline__ void mma16816(float* c, const uint32_t* a,
                                         uint32_t b0, uint32_t b1) {
    asm volatile(
        "mma.sync.aligned.m16n8k16.row.col.f32.f16.f16.f32 "
        "{%0,%1,%2,%3}, {%4,%5,%6,%7}, {%8,%9}, {%0,%1,%2,%3};"
        : "+f"(c[0]), "+f"(c[1]), "+f"(c[2]), "+f"(c[3])
        : "r"(a[0]), "r"(a[1]), "r"(a[2]), "r"(a[3]), "r"(b0), "r"(b1));
}

// ---------------- merged prep + conversion kernel ----------------
// block 0       : expert sort / tile tables / rowmap
// next XBLOCKS  : x fp32 -> fp16 (16 floats/thread, MLP=4)
// next W1BLOCKS : W1 transpose+convert (64k x 64n tiles, MLP=4)
// next W2BLOCKS : W2 transpose+convert
#define XBLOCKS  ((TOTAL_ROWS * N_IN) / 16 / 256)        // 1600
#define W1BLOCKS (((H_MID / 64) * (N_IN / 64)) * E_NUM)  // 1024
#define W2BLOCKS (((P_OUT / 64) * (H_MID / 64)) * E_NUM) // 1024
#define CONV_GRID (1 + XBLOCKS + W1BLOCKS + W2BLOCKS)

__device__ __forceinline__ void prep_body(const int* __restrict__ eid) {
    __shared__ int cnt[E_NUM], off[E_NUM];
    const int tid = threadIdx.x;
    if (tid < E_NUM) cnt[tid] = 0;
    __syncthreads();
    if (tid < B_TRIALS) atomicAdd(&cnt[eid[tid]], 1);
    __syncthreads();
    if (tid == 0) {
        int o = 0;
        for (int g = 0; g < E_NUM; g++) { off[g] = o; o += cnt[g]; }
        int c[E_NUM];
        for (int g = 0; g < E_NUM; g++) c[g] = 0;
        for (int i = 0; i < B_TRIALS; i++) {
            int g = eid[i];
            g_order[off[g] + c[g]++] = i;
        }
        int t = 0;
        for (int g = 0; g < E_NUM; g++) {
            int r0 = off[g] * F_BINS;
            int r1 = (off[g] + cnt[g]) * F_BINS;
            for (int r = r0; r < r1; r += 128)
                g_t128[t++] = make_int4(g, r, r1, 0);
        }
        g_n128 = t;
        for (; t < MAXT128; t++) g_t128[t] = make_int4(0, 0, 0, 0);
        t = 0;
        for (int g = 0; g < E_NUM; g++) {
            int r0 = off[g] * F_BINS;
            int r1 = (off[g] + cnt[g]) * F_BINS;
            for (int r = r0; r < r1; r += 64)
                g_t64[t++] = make_int4(g, r, r1, 0);
        }
        g_n64 = t;
        for (; t < MAXT64; t++) g_t64[t] = make_int4(0, 0, 0, 0);
    }
    __syncthreads();
    for (int j = tid; j < TOTAL_ROWS; j += blockDim.x)
        g_rowmap[j] = g_order[j / F_BINS] * F_BINS + (j % F_BINS);
}

// 64k x 64n transpose tile, 256 threads, 4 float4 loads/thread (MLP=4)
__device__ __forceinline__ void conv_w_tile(const float* __restrict__ W,
                                            __half* __restrict__ Wt,
                                            int K, int Nt, int bx, int by, int e) {
    __shared__ float t[64][65];
    int n0 = bx * 64;
    int k0 = by * 64;
    const float* src = W + ((size_t)e * K + k0) * Nt + n0;
    // load 64x64 floats = 1024 float4 / 256 threads = 4 each, all issued first
    float4 v[4];
#pragma unroll
    for (int it = 0; it < 4; it++) {
        int idx = it * 256 + threadIdx.x;
        int r   = idx >> 4;
        int c4  = (idx & 15) * 4;
        v[it] = *reinterpret_cast<const float4*>(src + (size_t)r * Nt + c4);
    }
#pragma unroll
    for (int it = 0; it < 4; it++) {
        int idx = it * 256 + threadIdx.x;
        int r   = idx >> 4;
        int c4  = (idx & 15) * 4;
        t[r][c4 + 0] = v[it].x;
        t[r][c4 + 1] = v[it].y;
        t[r][c4 + 2] = v[it].z;
        t[r][c4 + 3] = v[it].w;
    }
    __syncthreads();
    // store: 64 n x 8 kc-octets = 512 slots of 16B, 2 per thread
#pragma unroll
    for (int it = 0; it < 2; it++) {
        int slot = it * 256 + threadIdx.x;
        int n    = slot >> 3;
        int kc   = slot & 7;
        __half h[8];
#pragma unroll
        for (int j = 0; j < 8; j++) h[j] = __float2half_rn(t[kc * 8 + j][n]);
        *reinterpret_cast<uint4*>(Wt + ((size_t)e * Nt + n0 + n) * K + k0 + kc * 8) =
            *reinterpret_cast<uint4*>(h);
    }
}

__global__ void convert_all_kernel(const int* __restrict__ eid,
                                   const float* __restrict__ x,
                                   const float* __restrict__ W1,
                                   const float* __restrict__ W2,
                                   __half* __restrict__ xo,
                                   __half* __restrict__ w1o,
                                   __half* __restrict__ w2o) {
    int b = blockIdx.x;
    if (b == 0) {
        prep_body(eid);
    } else if (b <= XBLOCKS) {
        // 16 floats per thread: 4 float4 loads (MLP=4), 2 uint4 stores
        size_t i = ((size_t)(b - 1) * 256 + threadIdx.x) * 4;  // float4 index
        const float4* xp = reinterpret_cast<const float4*>(x) + i;
        float4 v0 = xp[0], v1 = xp[1], v2 = xp[2], v3 = xp[3];
        __half hb[16];
        hb[0]  = __float2half_rn(v0.x); hb[1]  = __float2half_rn(v0.y);
        hb[2]  = __float2half_rn(v0.z); hb[3]  = __float2half_rn(v0.w);
        hb[4]  = __float2half_rn(v1.x); hb[5]  = __float2half_rn(v1.y);
        hb[6]  = __float2half_rn(v1.z); hb[7]  = __float2half_rn(v1.w);
        hb[8]  = __float2half_rn(v2.x); hb[9]  = __float2half_rn(v2.y);
        hb[10] = __float2half_rn(v2.z); hb[11] = __float2half_rn(v2.w);
        hb[12] = __float2half_rn(v3.x); hb[13] = __float2half_rn(v3.y);
        hb[14] = __float2half_rn(v3.z); hb[15] = __float2half_rn(v3.w);
        uint4* xop = reinterpret_cast<uint4*>(xo) + i / 2;
        xop[0] = reinterpret_cast<uint4*>(hb)[0];
        xop[1] = reinterpret_cast<uint4*>(hb)[1];
    } else if (b <= XBLOCKS + W1BLOCKS) {
        int idx = b - 1 - XBLOCKS;
        int bx = idx % (H_MID / 64);
        int by = (idx / (H_MID / 64)) % (N_IN / 64);
        int e  = idx / ((H_MID / 64) * (N_IN / 64));
        conv_w_tile(W1, w1o, N_IN, H_MID, bx, by, e);
    } else {
        int idx = b - 1 - XBLOCKS - W1BLOCKS;
        int bx = idx % (P_OUT / 64);
        int by = (idx / (P_OUT / 64)) % (H_MID / 64);
        int e  = idx / ((P_OUT / 64) * (H_MID / 64));
        conv_w_tile(W2, w2o, H_MID, P_OUT, bx, by, e);
    }
}

// ---------------- grouped single-term fp16 mma.sync GEMM ----------------
// MT in {128, 64}; N tile 128; 256 threads; 2 CTAs/SM; 3-buffer single-sync
// pipeline; all addresses strength-reduced. (Frozen R11/R13 configuration.)
template <int MT, bool SOFTSIGN>
__global__ __launch_bounds__(256, 2)
void mma_gemm(const __half* __restrict__ Aw,
              const __half* __restrict__ Bw,
              const float* __restrict__ bias,
              float* __restrict__ outF,
              __half* __restrict__ outH,
              int K, int Ntot)
{
    constexpr int MWARPS = MT / 32;
    constexpr int NWARPS = 8 / MWARPS;
    constexpr int WARP_N = 128 / NWARPS;       // 64 or 32
    constexpr int NP     = WARP_N / 16;        // 4 or 2
    constexpr int NT8    = WARP_N / 8;         // 8 or 4
    constexpr uint32_t OFF_B = MT * 128;
    constexpr uint32_t STAGE = MT * 128 + 16384;
    constexpr int A_SLOTS = MT * 8;
    constexpr int SLOTS   = A_SLOTS + 1024;
    constexpr int ITERS   = SLOTS / 256;       // 8 or 6
    constexpr int A_ITERS = A_SLOTS / 256;     // 4 or 2

    const int ntiles = (MT == 128) ? g_n128 : g_n64;
    if ((int)blockIdx.y >= ntiles) return;
    const int4 tt     = (MT == 128) ? g_t128[blockIdx.y] : g_t64[blockIdx.y];
    const int  e      = tt.x;
    const int  row0   = tt.y;
    const int  rowend = tt.z;

    extern __shared__ __align__(1024) char smem[];
    __shared__ int rm[MT];
    const uint32_t sb = smem_to_u32(smem);
    const int tid = threadIdx.x;
    const int wid = tid >> 5;
    const int lid = tid & 31;
    const int wm  = wid % MWARPS;
    const int wn  = wid / MWARPS;
    const int n0  = blockIdx.x * 128;

    if (tid < MT) {
        const int r = row0 + tid;
        rm[tid] = (r < rowend) ? g_rowmap[r] : -1;
    }
    __syncthreads();

    // ---- one-time cp.async pointer/offset setup ----
    const __half* srcp[ITERS];
    uint32_t dsto[ITERS];
#pragma unroll
    for (int it = 0; it < ITERS; it++) {
        int slot = it * 256 + tid;
        if (it < A_ITERS) {
            int r = slot >> 3, c = slot & 7;
            int sr;
            if (SOFTSIGN) {
                sr = rm[r];
                if (sr < 0) sr = 0;
            } else {
                sr = row0 + r;
            }
            srcp[it] = Aw + (size_t)sr * K + c * 8;
            dsto[it] = SWZ128((uint32_t)(r * 128 + c * 16));
        } else {
            int idx = slot - A_SLOTS;
            int r = idx >> 3, c = idx & 7;
            srcp[it] = Bw + ((size_t)e * Ntot + n0 + r) * K + c * 8;
            dsto[it] = OFF_B + SWZ128((uint32_t)(r * 128 + c * 16));
        }
    }
    // ---- one-time LDSM offsets ----
    uint32_t offA[2][4], offB[NP][4];
#pragma unroll
    for (int kk = 0; kk < 4; kk++) {
        const uint32_t cb = (uint32_t)(kk * 32 + ((lid >> 4) << 4));
#pragma unroll
        for (int mt = 0; mt < 2; mt++)
            offA[mt][kk] =
                SWZ128((uint32_t)((wm * 32 + mt * 16 + (lid & 15)) * 128) + cb);
#pragma unroll
        for (int np = 0; np < NP; np++)
            offB[np][kk] = OFF_B +
                SWZ128((uint32_t)((wn * WARP_N + np * 16 + (lid & 15)) * 128) + cb);
    }

    const int nst = K >> 6;
    auto load_stage = [&](int s) {
        const uint32_t tb = sb + (uint32_t)(s % 3) * STAGE;
        const int koff = s << 6;
#pragma unroll
        for (int it = 0; it < ITERS; it++)
            cp16(tb + dsto[it], srcp[it] + koff);
        CP_COMMIT();
    };

    float acc[2][NT8][4];
#pragma unroll
    for (int mt = 0; mt < 2; mt++)
#pragma unroll
        for (int nt = 0; nt < NT8; nt++)
#pragma unroll
            for (int q = 0; q < 4; q++) acc[mt][nt][q] = 0.0f;

    load_stage(0);
    load_stage(1);

    for (int s = 0; s < nst; s++) {
        CP_WAIT1();
        __syncthreads();
        if (s + 2 < nst) load_stage(s + 2);
        else CP_COMMIT();

        const uint32_t base = sb + (uint32_t)(s % 3) * STAGE;
#pragma unroll
        for (int kk = 0; kk < 4; kk++) {
            uint32_t ah[2][4];
#pragma unroll
            for (int mt = 0; mt < 2; mt++)
                ldsm4(ah[mt], base + offA[mt][kk]);
#pragma unroll
            for (int np = 0; np < NP; np++) {
                uint32_t bh[4];
                ldsm4(bh, base + offB[np][kk]);
                const int nt0 = np * 2;
#pragma unroll
                for (int q = 0; q < 2; q++) {
                    mma16816(acc[0][nt0 + q], ah[0], bh[q], bh[2 + q]);
                    mma16816(acc[1][nt0 + q], ah[1], bh[q], bh[2 + q]);
                }
            }
        }
    }

    // ---------------- epilogue ----------------
    const int gq = lid >> 2;
    const int rq = lid & 3;
    float2 bv[NT8];
#pragma unroll
    for (int nt = 0; nt < NT8; nt++) {
        const int col = n0 + wn * WARP_N + nt * 8 + rq * 2;
        bv[nt] = *reinterpret_cast<const float2*>(bias + (size_t)e * Ntot + col);
    }

#pragma unroll
    for (int mt = 0; mt < 2; mt++) {
#pragma unroll
        for (int nt = 0; nt < NT8; nt++) {
            const int lr0 = wm * 32 + mt * 16 + gq;
            const int col = n0 + wn * WARP_N + nt * 8 + rq * 2;
            float c0 = acc[mt][nt][0] + bv[nt].x;
            float c1 = acc[mt][nt][1] + bv[nt].y;
            float c2 = acc[mt][nt][2] + bv[nt].x;
            float c3 = acc[mt][nt][3] + bv[nt].y;
            if (SOFTSIGN) {
                c0 = c0 / (1.0f + fabsf(c0));
                c1 = c1 / (1.0f + fabsf(c1));
                c2 = c2 / (1.0f + fabsf(c2));
                c3 = c3 / (1.0f + fabsf(c3));
                __half h0 = __float2half_rn(c0), h1 = __float2half_rn(c1);
                __half h2 = __float2half_rn(c2), h3 = __float2half_rn(c3);
                if (row0 + lr0 < rowend) {
                    size_t o0 = (size_t)(row0 + lr0) * Ntot + col;
                    *reinterpret_cast<__half2*>(outH + o0) = __half2(h0, h1);
                }
                if (row0 + lr0 + 8 < rowend) {
                    size_t o1 = (size_t)(row0 + lr0 + 8) * Ntot + col;
                    *reinterpret_cast<__half2*>(outH + o1) = __half2(h2, h3);
                }
            } else {
                const int d0 = rm[lr0];
                const int d1 = rm[lr0 + 8];
                if (d0 >= 0)
                    *reinterpret_cast<float2*>(outF + (size_t)d0 * Ntot + col) =
                        make_float2(c0, c1);
                if (d1 >= 0)
                    *reinterpret_cast<float2*>(outF + (size_t)d1 * Ntot + col) =
                        make_float2(c2, c3);
            }
        }
    }
}

// ---------------- host launcher ----------------
extern "C" void kernel_launch(void* const* d_in, const int* in_sizes, int n_in,
                              void* d_out, int out_size)
{
    const float* x   = (const float*)d_in[0];
    const int*   eid = (const int*)d_in[1];
    const float* W1  = (const float*)d_in[2];
    const float* b1  = (const float*)d_in[3];
    const float* W2  = (const float*)d_in[4];
    const float* b2  = (const float*)d_in[5];
    float* out = (float*)d_out;

    __half *xv, *w1, *w2, *av;
    cudaGetSymbolAddress((void**)&xv, g_x);
    cudaGetSymbolAddress((void**)&w1, g_w1);
    cudaGetSymbolAddress((void**)&w2, g_w2);
    cudaGetSymbolAddress((void**)&av, g_a);

    constexpr int SMEM1 = 3 * (128 * 128 + 16384);  // 98304
    constexpr int SMEM2 = 3 * (64 * 128 + 16384);   // 73728
    cudaFuncSetAttribute(mma_gemm<128, true>,
                         cudaFuncAttributeMaxDynamicSharedMemorySize, SMEM1);
    cudaFuncSetAttribute(mma_gemm<64, false>,
                         cudaFuncAttributeMaxDynamicSharedMemorySize, SMEM2);

    // 1) prep + all conversions in ONE launch (high-MLP paths)
    convert_all_kernel<<<CONV_GRID, 256>>>(eid, x, W1, W2, xv, w1, w2);
    // 2) GEMM1: M128xN128 tiles
    mma_gemm<128, true><<<dim3(H_MID / 128, MAXT128), 256, SMEM1>>>(
        xv, w1, b1, nullptr, av, /*K=*/N_IN, /*Ntot=*/H_MID);
    // 3) GEMM2: M64xN128 tiles
    mma_gemm<64, false><<<dim3(P_OUT / 128, MAXT64), 256, SMEM2>>>(
        av, w2, b2, out, nullptr, /*K=*/H_MID, /*Ntot=*/P_OUT);
}

// round 15
// speedup vs baseline: 1.0350x; 1.0350x over previous
#include <cuda_runtime.h>
#include <cuda_fp16.h>
#include <cstdint>

// Problem constants: E=8, N=512(K1), H=1024, P=512, F=100, B=128
#define E_NUM    8
#define B_TRIALS 128
#define F_BINS   100
#define N_IN     512
#define H_MID    1024
#define P_OUT    512
#define TOTAL_ROWS (B_TRIALS * F_BINS)   // 12800 packed rows
#define ACT_ROWS   13056                  // padded
#define MAXT64   224

// ---------------- device scratch ----------------
__device__ __half g_w1[(size_t)E_NUM * H_MID * N_IN];   // [E, N(out), K] K-major fp16
__device__ __half g_w2[(size_t)E_NUM * P_OUT * H_MID];
__device__ __half g_a[(size_t)ACT_ROWS * H_MID];        // act fp16, packed

__device__ int  g_order[B_TRIALS];
__device__ int  g_rowmap[TOTAL_ROWS];
__device__ int4 g_t64[MAXT64];
__device__ int  g_n64;

// ---------------- low-level helpers ----------------
__device__ __forceinline__ uint32_t smem_to_u32(const void* p) {
    uint32_t a;
    asm("{ .reg .u64 t; cvta.to.shared.u64 t, %1; cvt.u32.u64 %0, t; }"
        : "=r"(a) : "l"(p));
    return a;
}
#define SWZ128(o) ((o) ^ (((o) >> 3) & 0x70))

__device__ __forceinline__ void cp16(uint32_t dst, const void* src) {
    asm volatile("cp.async.cg.shared.global [%0], [%1], 16;"
                 :: "r"(dst), "l"(src) : "memory");
}
#define CP_COMMIT() asm volatile("cp.async.commit_group;" ::: "memory")
#define CP_WAIT1()  asm volatile("cp.async.wait_group 1;" ::: "memory")

__device__ __forceinline__ void ldsm4(uint32_t* r, uint32_t addr) {
    asm volatile("ldmatrix.sync.aligned.m8n8.x4.shared.b16 {%0,%1,%2,%3}, [%4];"
                 : "=r"(r[0]), "=r"(r[1]), "=r"(r[2]), "=r"(r[3]) : "r"(addr));
}
__device__ __forceinline__ void mma16816(float* c, const uint32_t* a,
                                         uint32_t b0, uint32_t b1) {
    asm volatile(
        "mma.sync.aligned.m16n8k16.row.col.f32.f16.f16.f32 "
        "{%0,%1,%2,%3}, {%4,%5,%6,%7}, {%8,%9}, {%0,%1,%2,%3};"
        : "+f"(c[0]), "+f"(c[1]), "+f"(c[2]), "+f"(c[3])
        : "r"(a[0]), "r"(a[1]), "r"(a[2]), "r"(a[3]), "r"(b0), "r"(b1));
}

// ---------------- merged prep + W conversion kernel (R13-proven shapes) ----------------
#define W1BLOCKS (((H_MID / 32) * (N_IN / 64)) * E_NUM)  // 2048
#define W2BLOCKS (((P_OUT / 32) * (H_MID / 64)) * E_NUM) // 2048
#define CONV_GRID (1 + W1BLOCKS + W2BLOCKS)

__device__ __forceinline__ void prep_body(const int* __restrict__ eid) {
    __shared__ int cnt[E_NUM], off[E_NUM];
    const int tid = threadIdx.x;
    if (tid < E_NUM) cnt[tid] = 0;
    __syncthreads();
    if (tid < B_TRIALS) atomicAdd(&cnt[eid[tid]], 1);
    __syncthreads();
    if (tid == 0) {
        int o = 0;
        for (int g = 0; g < E_NUM; g++) { off[g] = o; o += cnt[g]; }
        int c[E_NUM];
        for (int g = 0; g < E_NUM; g++) c[g] = 0;
        for (int i = 0; i < B_TRIALS; i++) {
            int g = eid[i];
            g_order[off[g] + c[g]++] = i;
        }
        int t = 0;
        for (int g = 0; g < E_NUM; g++) {
            int r0 = off[g] * F_BINS;
            int r1 = (off[g] + cnt[g]) * F_BINS;
            for (int r = r0; r < r1; r += 64)
                g_t64[t++] = make_int4(g, r, r1, 0);
        }
        g_n64 = t;
        for (; t < MAXT64; t++) g_t64[t] = make_int4(0, 0, 0, 0);
    }
    __syncthreads();
    for (int j = tid; j < TOTAL_ROWS; j += blockDim.x)
        g_rowmap[j] = g_order[j / F_BINS] * F_BINS + (j % F_BINS);
}

// 64k x 32n transpose tile, 256 threads (R13-proven)
__device__ __forceinline__ void conv_w_tile(const float* __restrict__ W,
                                            __half* __restrict__ Wt,
                                            int K, int Nt, int bx, int by, int e) {
    __shared__ float t[64][33];
    int n0 = bx * 32;
    int k0 = by * 64;
    const float* src = W + ((size_t)e * K + k0) * Nt + n0;
#pragma unroll
    for (int it = 0; it < 2; it++) {
        int idx = it * 256 + threadIdx.x;
        int r   = idx >> 3;
        int c4  = (idx & 7) * 4;
        float4 v = *reinterpret_cast<const float4*>(src + (size_t)r * Nt + c4);
        t[r][c4 + 0] = v.x;
        t[r][c4 + 1] = v.y;
        t[r][c4 + 2] = v.z;
        t[r][c4 + 3] = v.w;
    }
    __syncthreads();
    int n  = threadIdx.x >> 3;
    int kc = threadIdx.x & 7;
    __half h[8];
#pragma unroll
    for (int j = 0; j < 8; j++) h[j] = __float2half_rn(t[kc * 8 + j][n]);
    *reinterpret_cast<uint4*>(Wt + ((size_t)e * Nt + n0 + n) * K + k0 + kc * 8) =
        *reinterpret_cast<uint4*>(h);
}

__global__ void convert_all_kernel(const int* __restrict__ eid,
                                   const float* __restrict__ W1,
                                   const float* __restrict__ W2,
                                   __half* __restrict__ w1o,
                                   __half* __restrict__ w2o) {
    int b = blockIdx.x;
    if (b == 0) {
        prep_body(eid);
    } else if (b <= W1BLOCKS) {
        int idx = b - 1;
        int bx = idx % (H_MID / 32);
        int by = (idx / (H_MID / 32)) % (N_IN / 64);
        int e  = idx / ((H_MID / 32) * (N_IN / 64));
        conv_w_tile(W1, w1o, N_IN, H_MID, bx, by, e);
    } else {
        int idx = b - 1 - W1BLOCKS;
        int bx = idx % (P_OUT / 32);
        int by = (idx / (P_OUT / 32)) % (H_MID / 64);
        int e  = idx / ((P_OUT / 32) * (H_MID / 64));
        conv_w_tile(W2, w2o, H_MID, P_OUT, bx, by, e);
    }
}

// ---------------- GEMM1: fused fp32->fp16 A conversion ----------------
// M64 x N128; 256 threads (8 warps, warp 32x32); 2 CTAs/SM.
// A: fp32 gathered rows LDG (prefetched 1 stage ahead) -> cvt -> STS fp16.
// B: cp.async fp16, 3-stage. Epilogue: bias + softsign -> packed act fp16.
#define G1_OFF_B  8192u
#define G1_STAGE  24576u
__global__ __launch_bounds__(256, 2)
void mma_gemm1(const float* __restrict__ Xf,
               const __half* __restrict__ Bw,
               const float* __restrict__ bias,
               __half* __restrict__ outH)
{
    constexpr int K = N_IN, Ntot = H_MID;
    constexpr int NP = 2, NT8 = 4, WARP_N = 32;

    if ((int)blockIdx.y >= g_n64) return;
    const int4 tt     = g_t64[blockIdx.y];
    const int  e      = tt.x;
    const int  row0   = tt.y;
    const int  rowend = tt.z;

    extern __shared__ __align__(1024) char smem[];
    __shared__ int rm[64];
    const uint32_t sb = smem_to_u32(smem);
    const int tid = threadIdx.x;
    const int wid = tid >> 5;
    const int lid = tid & 31;
    const int wm  = wid & 1;
    const int wn  = wid >> 1;
    const int n0  = blockIdx.x * 128;

    if (tid < 64) {
        const int r = row0 + tid;
        rm[tid] = (r < rowend) ? g_rowmap[r] : -1;
    }
    __syncthreads();

    // A: 512 slots of 8 halves; thread owns slots tid, tid+256
    const float* xsrc[2];
    uint32_t dstA[2];
#pragma unroll
    for (int i = 0; i < 2; i++) {
        int slot = i * 256 + tid;
        int r = slot >> 3, c = slot & 7;
        int sr = rm[r];
        if (sr < 0) sr = 0;                  // padded rows: real data, discarded later
        xsrc[i] = Xf + (size_t)sr * K + c * 8;
        dstA[i] = SWZ128((uint32_t)(r * 128 + c * 16));
    }
    // B: 1024 slots, 4 per thread
    const __half* bsrc[4];
    uint32_t dstB[4];
#pragma unroll
    for (int i = 0; i < 4; i++) {
        int idx = i * 256 + tid;
        int r = idx >> 3, c = idx & 7;
        bsrc[i] = Bw + ((size_t)e * Ntot + n0 + r) * K + c * 8;
        dstB[i] = G1_OFF_B + SWZ128((uint32_t)(r * 128 + c * 16));
    }
    // LDSM offsets
    uint32_t offA[2][4], offB[NP][4];
#pragma unroll
    for (int kk = 0; kk < 4; kk++) {
        const uint32_t cb = (uint32_t)(kk * 32 + ((lid >> 4) << 4));
#pragma unroll
        for (int mt = 0; mt < 2; mt++)
            offA[mt][kk] =
                SWZ128((uint32_t)((wm * 32 + mt * 16 + (lid & 15)) * 128) + cb);
#pragma unroll
        for (int np = 0; np < NP; np++)
            offB[np][kk] = G1_OFF_B +
                SWZ128((uint32_t)((wn * WARP_N + np * 16 + (lid & 15)) * 128) + cb);
    }

    constexpr int nst = K >> 6;   // 8
    auto loadB = [&](int s) {
        const uint32_t tb = sb + (uint32_t)(s % 3) * G1_STAGE;
        const int koff = s << 6;
#pragma unroll
        for (int i = 0; i < 4; i++) cp16(tb + dstB[i], bsrc[i] + koff);
        CP_COMMIT();
    };

    float4 va[2][2];
    auto ldgA = [&](int s) {
        const int koff = s << 6;
#pragma unroll
        for (int i = 0; i < 2; i++) {
            va[i][0] = *reinterpret_cast<const float4*>(xsrc[i] + koff);
            va[i][1] = *reinterpret_cast<const float4*>(xsrc[i] + koff + 4);
        }
    };
    auto stsA = [&](int s) {
        const uint32_t tb = sb + (uint32_t)(s % 3) * G1_STAGE;
#pragma unroll
        for (int i = 0; i < 2; i++) {
            __half h[8];
            h[0] = __float2half_rn(va[i][0].x); h[1] = __float2half_rn(va[i][0].y);
            h[2] = __float2half_rn(va[i][0].z); h[3] = __float2half_rn(va[i][0].w);
            h[4] = __float2half_rn(va[i][1].x); h[5] = __float2half_rn(va[i][1].y);
            h[6] = __float2half_rn(va[i][1].z); h[7] = __float2half_rn(va[i][1].w);
            *reinterpret_cast<uint4*>(smem + (tb - sb) + dstA[i]) =
                *reinterpret_cast<uint4*>(h);
        }
    };

    float acc[2][NT8][4];
#pragma unroll
    for (int mt = 0; mt < 2; mt++)
#pragma unroll
        for (int nt = 0; nt < NT8; nt++)
#pragma unroll
            for (int q = 0; q < 4; q++) acc[mt][nt][q] = 0.0f;

    loadB(0);
    loadB(1);
    ldgA(0);

    for (int s = 0; s < nst; s++) {
        CP_WAIT1();           // B(s) resident
        __syncthreads();      // compute(s-1) complete everywhere
        stsA(s);              // fp16 A into buffer s%3 (free: consumed at s-1)
        if (s + 2 < nst) loadB(s + 2);
        else CP_COMMIT();
        if (s + 1 < nst) ldgA(s + 1);   // prefetch next A regs (covered by compute)
        __syncthreads();      // A STS visible for ldmatrix

        const uint32_t base = sb + (uint32_t)(s % 3) * G1_STAGE;
#pragma unroll
        for (int kk = 0; kk < 4; kk++) {
            uint32_t ah[2][4];
#pragma unroll
            for (int mt = 0; mt < 2; mt++)
                ldsm4(ah[mt], base + offA[mt][kk]);
#pragma unroll
            for (int np = 0; np < NP; np++) {
                uint32_t bh[4];
                ldsm4(bh, base + offB[np][kk]);
                const int nt0 = np * 2;
#pragma unroll
                for (int q = 0; q < 2; q++) {
                    mma16816(acc[0][nt0 + q], ah[0], bh[q], bh[2 + q]);
                    mma16816(acc[1][nt0 + q], ah[1], bh[q], bh[2 + q]);
                }
            }
        }
    }

    // ---- epilogue: bias + softsign -> packed act ----
    const int gq = lid >> 2;
    const int rq = lid & 3;
    float2 bv[NT8];
#pragma unroll
    for (int nt = 0; nt < NT8; nt++) {
        const int col = n0 + wn * WARP_N + nt * 8 + rq * 2;
        bv[nt] = *reinterpret_cast<const float2*>(bias + (size_t)e * Ntot + col);
    }
#pragma unroll
    for (int mt = 0; mt < 2; mt++) {
#pragma unroll
        for (int nt = 0; nt < NT8; nt++) {
            const int lr0 = wm * 32 + mt * 16 + gq;
            const int col = n0 + wn * WARP_N + nt * 8 + rq * 2;
            float c0 = acc[mt][nt][0] + bv[nt].x;
            float c1 = acc[mt][nt][1] + bv[nt].y;
            float c2 = acc[mt][nt][2] + bv[nt].x;
            float c3 = acc[mt][nt][3] + bv[nt].y;
            c0 = c0 / (1.0f + fabsf(c0));
            c1 = c1 / (1.0f + fabsf(c1));
            c2 = c2 / (1.0f + fabsf(c2));
            c3 = c3 / (1.0f + fabsf(c3));
            __half h0 = __float2half_rn(c0), h1 = __float2half_rn(c1);
            __half h2 = __float2half_rn(c2), h3 = __float2half_rn(c3);
            if (row0 + lr0 < rowend) {
                size_t o0 = (size_t)(row0 + lr0) * Ntot + col;
                *reinterpret_cast<__half2*>(outH + o0) = __half2(h0, h1);
            }
            if (row0 + lr0 + 8 < rowend) {
                size_t o1 = (size_t)(row0 + lr0 + 8) * Ntot + col;
                *reinterpret_cast<__half2*>(outH + o1) = __half2(h2, h3);
            }
        }
    }
}

// ---------------- GEMM2: plain fp16 (frozen R11/R13 path, MT=64) ----------------
#define G2_OFF_B  8192u
#define G2_STAGE  24576u
__global__ __launch_bounds__(256, 2)
void mma_gemm2(const __half* __restrict__ Aw,
               const __half* __restrict__ Bw,
               const float* __restrict__ bias,
               float* __restrict__ outF)
{
    constexpr int K = H_MID, Ntot = P_OUT;
    constexpr int NP = 2, NT8 = 4, WARP_N = 32;
    constexpr int ITERS = 6, A_ITERS = 2;
    constexpr int A_SLOTS = 512;

    if ((int)blockIdx.y >= g_n64) return;
    const int4 tt     = g_t64[blockIdx.y];
    const int  e      = tt.x;
    const int  row0   = tt.y;

    extern __shared__ __align__(1024) char smem[];
    __shared__ int rm[64];
    const uint32_t sb = smem_to_u32(smem);
    const int tid = threadIdx.x;
    const int wid = tid >> 5;
    const int lid = tid & 31;
    const int wm  = wid & 1;
    const int wn  = wid >> 1;
    const int n0  = blockIdx.x * 128;

    if (tid < 64) {
        const int r = row0 + tid;
        rm[tid] = (r < tt.z) ? g_rowmap[r] : -1;
    }
    __syncthreads();

    const __half* srcp[ITERS];
    uint32_t dsto[ITERS];
#pragma unroll
    for (int it = 0; it < ITERS; it++) {
        int slot = it * 256 + tid;
        if (it < A_ITERS) {
            int r = slot >> 3, c = slot & 7;
            srcp[it] = Aw + (size_t)(row0 + r) * K + c * 8;
            dsto[it] = SWZ128((uint32_t)(r * 128 + c * 16));
        } else {
            int idx = slot - A_SLOTS;
            int r = idx >> 3, c = idx & 7;
            srcp[it] = Bw + ((size_t)e * Ntot + n0 + r) * K + c * 8;
            dsto[it] = G2_OFF_B + SWZ128((uint32_t)(r * 128 + c * 16));
        }
    }
    uint32_t offA[2][4], offB[NP][4];
#pragma unroll
    for (int kk = 0; kk < 4; kk++) {
        const uint32_t cb = (uint32_t)(kk * 32 + ((lid >> 4) << 4));
#pragma unroll
        for (int mt = 0; mt < 2; mt++)
            offA[mt][kk] =
                SWZ128((uint32_t)((wm * 32 + mt * 16 + (lid & 15)) * 128) + cb);
#pragma unroll
        for (int np = 0; np < NP; np++)
            offB[np][kk] = G2_OFF_B +
                SWZ128((uint32_t)((wn * WARP_N + np * 16 + (lid & 15)) * 128) + cb);
    }

    constexpr int nst = K >> 6;   // 16
    auto load_stage = [&](int s) {
        const uint32_t tb = sb + (uint32_t)(s % 3) * G2_STAGE;
        const int koff = s << 6;
#pragma unroll
        for (int it = 0; it < ITERS; it++)
            cp16(tb + dsto[it], srcp[it] + koff);
        CP_COMMIT();
    };

    float acc[2][NT8][4];
#pragma unroll
    for (int mt = 0; mt < 2; mt++)
#pragma unroll
        for (int nt = 0; nt < NT8; nt++)
#pragma unroll
            for (int q = 0; q < 4; q++) acc[mt][nt][q] = 0.0f;

    load_stage(0);
    load_stage(1);

    for (int s = 0; s < nst; s++) {
        CP_WAIT1();
        __syncthreads();
        if (s + 2 < nst) load_stage(s + 2);
        else CP_COMMIT();

        const uint32_t base = sb + (uint32_t)(s % 3) * G2_STAGE;
#pragma unroll
        for (int kk = 0; kk < 4; kk++) {
            uint32_t ah[2][4];
#pragma unroll
            for (int mt = 0; mt < 2; mt++)
                ldsm4(ah[mt], base + offA[mt][kk]);
#pragma unroll
            for (int np = 0; np < NP; np++) {
                uint32_t bh[4];
                ldsm4(bh, base + offB[np][kk]);
                const int nt0 = np * 2;
#pragma unroll
                for (int q = 0; q < 2; q++) {
                    mma16816(acc[0][nt0 + q], ah[0], bh[q], bh[2 + q]);
                    mma16816(acc[1][nt0 + q], ah[1], bh[q], bh[2 + q]);
                }
            }
        }
    }

    const int gq = lid >> 2;
    const int rq = lid & 3;
    float2 bv[NT8];
#pragma unroll
    for (int nt = 0; nt < NT8; nt++) {
        const int col = n0 + wn * WARP_N + nt * 8 + rq * 2;
        bv[nt] = *reinterpret_cast<const float2*>(bias + (size_t)e * Ntot + col);
    }
#pragma unroll
    for (int mt = 0; mt < 2; mt++) {
#pragma unroll
        for (int nt = 0; nt < NT8; nt++) {
            const int lr0 = wm * 32 + mt * 16 + gq;
            const int col = n0 + wn * WARP_N + nt * 8 + rq * 2;
            float c0 = acc[mt][nt][0] + bv[nt].x;
            float c1 = acc[mt][nt][1] + bv[nt].y;
            float c2 = acc[mt][nt][2] + bv[nt].x;
            float c3 = acc[mt][nt][3] + bv[nt].y;
            const int d0 = rm[lr0];
            const int d1 = rm[lr0 + 8];
            if (d0 >= 0)
                *reinterpret_cast<float2*>(outF + (size_t)d0 * Ntot + col) =
                    make_float2(c0, c1);
            if (d1 >= 0)
                *reinterpret_cast<float2*>(outF + (size_t)d1 * Ntot + col) =
                    make_float2(c2, c3);
        }
    }
}

// ---------------- host launcher ----------------
extern "C" void kernel_launch(void* const* d_in, const int* in_sizes, int n_in,
                              void* d_out, int out_size)
{
    const float* x   = (const float*)d_in[0];
    const int*   eid = (const int*)d_in[1];
    const float* W1  = (const float*)d_in[2];
    const float* b1  = (const float*)d_in[3];
    const float* W2  = (const float*)d_in[4];
    const float* b2  = (const float*)d_in[5];
    float* out = (float*)d_out;

    __half *w1, *w2, *av;
    cudaGetSymbolAddress((void**)&w1, g_w1);
    cudaGetSymbolAddress((void**)&w2, g_w2);
    cudaGetSymbolAddress((void**)&av, g_a);

    constexpr int SMEM = 3 * 24576;   // 73728
    cudaFuncSetAttribute(mma_gemm1,
                         cudaFuncAttributeMaxDynamicSharedMemorySize, SMEM);
    cudaFuncSetAttribute(mma_gemm2,
                         cudaFuncAttributeMaxDynamicSharedMemorySize, SMEM);

    // 1) prep + W conversions (x staging eliminated)
    convert_all_kernel<<<CONV_GRID, 256>>>(eid, W1, W2, w1, w2);
    // 2) GEMM1: fused fp32 gather+convert, M64xN128
    mma_gemm1<<<dim3(H_MID / 128, MAXT64), 256, SMEM>>>(x, w1, b1, av);
    // 3) GEMM2: M64xN128
    mma_gemm2<<<dim3(P_OUT / 128, MAXT64), 256, SMEM>>>(av, w2, b2, out);
}

// round 16
// speedup vs baseline: 1.1085x; 1.0711x over previous
#include <cuda_runtime.h>
#include <cuda_fp16.h>
#include <cstdint>

// Problem constants: E=8, N=512(K1), H=1024, P=512, F=100, B=128
#define E_NUM    8
#define B_TRIALS 128
#define F_BINS   100
#define N_IN     512
#define H_MID    1024
#define P_OUT    512
#define TOTAL_ROWS (B_TRIALS * F_BINS)   // 12800 packed rows
#define ACT_ROWS   13056                  // padded
#define MAXT128  120
#define MAXT64   224

// ---------------- device scratch ----------------
__device__ __half g_x[(size_t)TOTAL_ROWS * N_IN];
__device__ __half g_w1[(size_t)E_NUM * H_MID * N_IN];   // [E, N(out), K] K-major fp16
__device__ __half g_w2[(size_t)E_NUM * P_OUT * H_MID];
__device__ __half g_a[(size_t)ACT_ROWS * H_MID];        // act fp16, packed

__device__ int  g_order[B_TRIALS];
__device__ int  g_rowmap[TOTAL_ROWS];
__device__ int4 g_t128[MAXT128];
__device__ int  g_n128;
__device__ int4 g_t64[MAXT64];
__device__ int  g_n64;

// ---------------- low-level helpers ----------------
__device__ __forceinline__ uint32_t smem_to_u32(const void* p) {
    uint32_t a;
    asm("{ .reg .u64 t; cvta.to.shared.u64 t, %1; cvt.u32.u64 %0, t; }"
        : "=r"(a) : "l"(p));
    return a;
}
#define SWZ128(o) ((o) ^ (((o) >> 3) & 0x70))

__device__ __forceinline__ void cp16(uint32_t dst, const void* src) {
    asm volatile("cp.async.cg.shared.global [%0], [%1], 16;"
                 :: "r"(dst), "l"(src) : "memory");
}
#define CP_COMMIT() asm volatile("cp.async.commit_group;" ::: "memory")
#define CP_WAIT1()  asm volatile("cp.async.wait_group 1;" ::: "memory")

__device__ __forceinline__ void ldsm4(uint32_t* r, uint32_t addr) {
    asm volatile("ldmatrix.sync.aligned.m8n8.x4.shared.b16 {%0,%1,%2,%3}, [%4];"
                 : "=r"(r[0]), "=r"(r[1]), "=r"(r[2]), "=r"(r[3]) : "r"(addr));
}
__device__ __forceinline__ void mma16816(float* c, const uint32_t* a,
                                         uint32_t b0, uint32_t b1) {
    asm volatile(
        "mma.sync.aligned.m16n8k16.row.col.f32.f16.f16.f32 "
        "{%0,%1,%2,%3}, {%4,%5,%6,%7}, {%8,%9}, {%0,%1,%2,%3};"
        : "+f"(c[0]), "+f"(c[1]), "+f"(c[2]), "+f"(c[3])
        : "r"(a[0]), "r"(a[1]), "r"(a[2]), "r"(a[3]), "r"(b0), "r"(b1));
}

// ---------------- prep body ----------------
__device__ __forceinline__ void prep_body(const int* __restrict__ eid) {
    __shared__ int cnt[E_NUM], off[E_NUM];
    const int tid = threadIdx.x;
    if (tid < E_NUM) cnt[tid] = 0;
    __syncthreads();
    if (tid < B_TRIALS) atomicAdd(&cnt[eid[tid]], 1);
    __syncthreads();
    if (tid == 0) {
        int o = 0;
        for (int g = 0; g < E_NUM; g++) { off[g] = o; o += cnt[g]; }
        int c[E_NUM];
        for (int g = 0; g < E_NUM; g++) c[g] = 0;
        for (int i = 0; i < B_TRIALS; i++) {
            int g = eid[i];
            g_order[off[g] + c[g]++] = i;
        }
        int t = 0;
        for (int g = 0; g < E_NUM; g++) {
            int r0 = off[g] * F_BINS;
            int r1 = (off[g] + cnt[g]) * F_BINS;
            for (int r = r0; r < r1; r += 128)
                g_t128[t++] = make_int4(g, r, r1, 0);
        }
        g_n128 = t;
        for (; t < MAXT128; t++) g_t128[t] = make_int4(0, 0, 0, 0);
        t = 0;
        for (int g = 0; g < E_NUM; g++) {
            int r0 = off[g] * F_BINS;
            int r1 = (off[g] + cnt[g]) * F_BINS;
            for (int r = r0; r < r1; r += 64)
                g_t64[t++] = make_int4(g, r, r1, 0);
        }
        g_n64 = t;
        for (; t < MAXT64; t++) g_t64[t] = make_int4(0, 0, 0, 0);
    }
    __syncthreads();
    for (int j = tid; j < TOTAL_ROWS; j += blockDim.x)
        g_rowmap[j] = g_order[j / F_BINS] * F_BINS + (j % F_BINS);
}

// W transpose tile (R13-proven): 64 k-rows x 32 n-cols, 256 threads.
// smem buffer supplied by caller (>= 64*33*4 = 8448 bytes).
__device__ __forceinline__ void conv_w_tile(float (*t)[33],
                                            const float* __restrict__ W,
                                            __half* __restrict__ Wt,
                                            int K, int Nt, int bx, int by, int e) {
    int n0 = bx * 32;
    int k0 = by * 64;
    const float* src = W + ((size_t)e * K + k0) * Nt + n0;
#pragma unroll
    for (int it = 0; it < 2; it++) {
        int idx = it * 256 + threadIdx.x;
        int r   = idx >> 3;
        int c4  = (idx & 7) * 4;
        float4 v = *reinterpret_cast<const float4*>(src + (size_t)r * Nt + c4);
        t[r][c4 + 0] = v.x;
        t[r][c4 + 1] = v.y;
        t[r][c4 + 2] = v.z;
        t[r][c4 + 3] = v.w;
    }
    __syncthreads();
    int n  = threadIdx.x >> 3;
    int kc = threadIdx.x & 7;
    __half h[8];
#pragma unroll
    for (int j = 0; j < 8; j++) h[j] = __float2half_rn(t[kc * 8 + j][n]);
    *reinterpret_cast<uint4*>(Wt + ((size_t)e * Nt + n0 + n) * K + k0 + kc * 8) =
        *reinterpret_cast<uint4*>(h);
}

// ---------------- launch 1: prep + x convert + W1 convert ----------------
#define XBLOCKS  ((TOTAL_ROWS * N_IN) / 8 / 256)         // 3200
#define W1BLOCKS (((H_MID / 32) * (N_IN / 64)) * E_NUM)  // 2048
#define W2BLOCKS (((P_OUT / 32) * (H_MID / 64)) * E_NUM) // 2048
#define CONV_GRID (1 + XBLOCKS + W1BLOCKS)

__global__ void convert_all_kernel(const int* __restrict__ eid,
                                   const float* __restrict__ x,
                                   const float* __restrict__ W1,
                                   __half* __restrict__ xo,
                                   __half* __restrict__ w1o) {
    __shared__ float t[64][33];
    int b = blockIdx.x;
    if (b == 0) {
        prep_body(eid);
    } else if (b <= XBLOCKS) {
        int i = (b - 1) * 256 + threadIdx.x;   // 8-float chunk
        const float4* xp = reinterpret_cast<const float4*>(x) + (size_t)i * 2;
        float4 v0 = xp[0];
        float4 v1 = xp[1];
        __half hb[8];
        hb[0] = __float2half_rn(v0.x); hb[1] = __float2half_rn(v0.y);
        hb[2] = __float2half_rn(v0.z); hb[3] = __float2half_rn(v0.w);
        hb[4] = __float2half_rn(v1.x); hb[5] = __float2half_rn(v1.y);
        hb[6] = __float2half_rn(v1.z); hb[7] = __float2half_rn(v1.w);
        reinterpret_cast<uint4*>(xo)[i] = *reinterpret_cast<uint4*>(hb);
    } else {
        int idx = b - 1 - XBLOCKS;
        int bx = idx % (H_MID / 32);
        int by = (idx / (H_MID / 32)) % (N_IN / 64);
        int e  = idx / ((H_MID / 32) * (N_IN / 64));
        conv_w_tile(t, W1, w1o, N_IN, H_MID, bx, by, e);
    }
}

// ---------------- GEMM body (R13/R11 frozen config) ----------------
template <int MT, bool SOFTSIGN>
__device__ __forceinline__ void gemm_body(
    int bx, int by,
    const __half* __restrict__ Aw, const __half* __restrict__ Bw,
    const float* __restrict__ bias,
    float* __restrict__ outF, __half* __restrict__ outH,
    int K, int Ntot, char* smem)
{
    constexpr int MWARPS = MT / 32;
    constexpr int NWARPS = 8 / MWARPS;
    constexpr int WARP_N = 128 / NWARPS;
    constexpr int NP     = WARP_N / 16;
    constexpr int NT8    = WARP_N / 8;
    constexpr uint32_t OFF_B = MT * 128;
    constexpr uint32_t STAGE = MT * 128 + 16384;
    constexpr int A_SLOTS = MT * 8;
    constexpr int SLOTS   = A_SLOTS + 1024;
    constexpr int ITERS   = SLOTS / 256;
    constexpr int A_ITERS = A_SLOTS / 256;

    const int ntiles = (MT == 128) ? g_n128 : g_n64;
    if (by >= ntiles) return;
    const int4 tt     = (MT == 128) ? g_t128[by] : g_t64[by];
    const int  e      = tt.x;
    const int  row0   = tt.y;
    const int  rowend = tt.z;

    __shared__ int rm[MT];
    const uint32_t sb = smem_to_u32(smem);
    const int tid = threadIdx.x;
    const int wid = tid >> 5;
    const int lid = tid & 31;
    const int wm  = wid % MWARPS;
    const int wn  = wid / MWARPS;
    const int n0  = bx * 128;

    if (tid < MT) {
        const int r = row0 + tid;
        rm[tid] = (r < rowend) ? g_rowmap[r] : -1;
    }
    __syncthreads();

    const __half* srcp[ITERS];
    uint32_t dsto[ITERS];
#pragma unroll
    for (int it = 0; it < ITERS; it++) {
        int slot = it * 256 + tid;
        if (it < A_ITERS) {
            int r = slot >> 3, c = slot & 7;
            int sr;
            if (SOFTSIGN) {
                sr = rm[r];
                if (sr < 0) sr = 0;
            } else {
                sr = row0 + r;
            }
            srcp[it] = Aw + (size_t)sr * K + c * 8;
            dsto[it] = SWZ128((uint32_t)(r * 128 + c * 16));
        } else {
            int idx = slot - A_SLOTS;
            int r = idx >> 3, c = idx & 7;
            srcp[it] = Bw + ((size_t)e * Ntot + n0 + r) * K + c * 8;
            dsto[it] = OFF_B + SWZ128((uint32_t)(r * 128 + c * 16));
        }
    }
    uint32_t offA[2][4], offB[NP][4];
#pragma unroll
    for (int kk = 0; kk < 4; kk++) {
        const uint32_t cb = (uint32_t)(kk * 32 + ((lid >> 4) << 4));
#pragma unroll
        for (int mt = 0; mt < 2; mt++)
            offA[mt][kk] =
                SWZ128((uint32_t)((wm * 32 + mt * 16 + (lid & 15)) * 128) + cb);
#pragma unroll
        for (int np = 0; np < NP; np++)
            offB[np][kk] = OFF_B +
                SWZ128((uint32_t)((wn * WARP_N + np * 16 + (lid & 15)) * 128) + cb);
    }

    const int nst = K >> 6;
    auto load_stage = [&](int s) {
        const uint32_t tb = sb + (uint32_t)(s % 3) * STAGE;
        const int koff = s << 6;
#pragma unroll
        for (int it = 0; it < ITERS; it++)
            cp16(tb + dsto[it], srcp[it] + koff);
        CP_COMMIT();
    };

    float acc[2][NT8][4];
#pragma unroll
    for (int mt = 0; mt < 2; mt++)
#pragma unroll
        for (int nt = 0; nt < NT8; nt++)
#pragma unroll
            for (int q = 0; q < 4; q++) acc[mt][nt][q] = 0.0f;

    load_stage(0);
    load_stage(1);

    for (int s = 0; s < nst; s++) {
        CP_WAIT1();
        __syncthreads();
        if (s + 2 < nst) load_stage(s + 2);
        else CP_COMMIT();

        const uint32_t base = sb + (uint32_t)(s % 3) * STAGE;
#pragma unroll
        for (int kk = 0; kk < 4; kk++) {
            uint32_t ah[2][4];
#pragma unroll
            for (int mt = 0; mt < 2; mt++)
                ldsm4(ah[mt], base + offA[mt][kk]);
#pragma unroll
            for (int np = 0; np < NP; np++) {
                uint32_t bh[4];
                ldsm4(bh, base + offB[np][kk]);
                const int nt0 = np * 2;
#pragma unroll
                for (int q = 0; q < 2; q++) {
                    mma16816(acc[0][nt0 + q], ah[0], bh[q], bh[2 + q]);
                    mma16816(acc[1][nt0 + q], ah[1], bh[q], bh[2 + q]);
                }
            }
        }
    }

    const int gq = lid >> 2;
    const int rq = lid & 3;
    float2 bv[NT8];
#pragma unroll
    for (int nt = 0; nt < NT8; nt++) {
        const int col = n0 + wn * WARP_N + nt * 8 + rq * 2;
        bv[nt] = *reinterpret_cast<const float2*>(bias + (size_t)e * Ntot + col);
    }
#pragma unroll
    for (int mt = 0; mt < 2; mt++) {
#pragma unroll
        for (int nt = 0; nt < NT8; nt++) {
            const int lr0 = wm * 32 + mt * 16 + gq;
            const int col = n0 + wn * WARP_N + nt * 8 + rq * 2;
            float c0 = acc[mt][nt][0] + bv[nt].x;
            float c1 = acc[mt][nt][1] + bv[nt].y;
            float c2 = acc[mt][nt][2] + bv[nt].x;
            float c3 = acc[mt][nt][3] + bv[nt].y;
            if (SOFTSIGN) {
                c0 = c0 / (1.0f + fabsf(c0));
                c1 = c1 / (1.0f + fabsf(c1));
                c2 = c2 / (1.0f + fabsf(c2));
                c3 = c3 / (1.0f + fabsf(c3));
                __half h0 = __float2half_rn(c0), h1 = __float2half_rn(c1);
                __half h2 = __float2half_rn(c2), h3 = __float2half_rn(c3);
                if (row0 + lr0 < rowend) {
                    size_t o0 = (size_t)(row0 + lr0) * Ntot + col;
                    *reinterpret_cast<__half2*>(outH + o0) = __half2(h0, h1);
                }
                if (row0 + lr0 + 8 < rowend) {
                    size_t o1 = (size_t)(row0 + lr0 + 8) * Ntot + col;
                    *reinterpret_cast<__half2*>(outH + o1) = __half2(h2, h3);
                }
            } else {
                const int d0 = rm[lr0];
                const int d1 = rm[lr0 + 8];
                if (d0 >= 0)
                    *reinterpret_cast<float2*>(outF + (size_t)d0 * Ntot + col) =
                        make_float2(c0, c1);
                if (d1 >= 0)
                    *reinterpret_cast<float2*>(outF + (size_t)d1 * Ntot + col) =
                        make_float2(c2, c3);
            }
        }
    }
}

// ---------------- launch 2: GEMM1 (MT128) + W2 conversion blocks ----------------
#define G1_BLOCKS ((H_MID / 128) * MAXT128)   // 960
#define G1_GRID   (G1_BLOCKS + W2BLOCKS)      // 3008

__global__ __launch_bounds__(256, 2)
void gemm1_plus_w2(const __half* __restrict__ Aw, const __half* __restrict__ Bw,
                   const float* __restrict__ bias, __half* __restrict__ outH,
                   const float* __restrict__ W2f, __half* __restrict__ w2o)
{
    extern __shared__ __align__(1024) char smem[];
    int b = blockIdx.x;
    if (b >= G1_BLOCKS) {
        // W2 conversion block (memory-bound; fills GEMM bubbles/tail)
        int idx = b - G1_BLOCKS;
        int bx = idx % (P_OUT / 32);
        int by = (idx / (P_OUT / 32)) % (H_MID / 64);
        int e  = idx / ((P_OUT / 32) * (H_MID / 64));
        conv_w_tile(reinterpret_cast<float(*)[33]>(smem), W2f, w2o,
                    H_MID, P_OUT, bx, by, e);
        return;
    }
    const int bx = b % (H_MID / 128);   // 8 n-tiles
    const int by = b / (H_MID / 128);
    gemm_body<128, true>(bx, by, Aw, Bw, bias, nullptr, outH,
                         /*K=*/N_IN, /*Ntot=*/H_MID, smem);
}

// ---------------- launch 3: GEMM2 (MT64) ----------------
__global__ __launch_bounds__(256, 2)
void gemm2_kernel(const __half* __restrict__ Aw, const __half* __restrict__ Bw,
                  const float* __restrict__ bias, float* __restrict__ outF)
{
    extern __shared__ __align__(1024) char smem[];
    gemm_body<64, false>(blockIdx.x, blockIdx.y, Aw, Bw, bias, outF, nullptr,
                         /*K=*/H_MID, /*Ntot=*/P_OUT, smem);
}

// ---------------- host launcher ----------------
extern "C" void kernel_launch(void* const* d_in, const int* in_sizes, int n_in,
                              void* d_out, int out_size)
{
    const float* x   = (const float*)d_in[0];
    const int*   eid = (const int*)d_in[1];
    const float* W1  = (const float*)d_in[2];
    const float* b1  = (const float*)d_in[3];
    const float* W2  = (const float*)d_in[4];
    const float* b2  = (const float*)d_in[5];
    float* out = (float*)d_out;

    __half *xv, *w1, *w2, *av;
    cudaGetSymbolAddress((void**)&xv, g_x);
    cudaGetSymbolAddress((void**)&w1, g_w1);
    cudaGetSymbolAddress((void**)&w2, g_w2);
    cudaGetSymbolAddress((void**)&av, g_a);

    constexpr int SMEM1 = 3 * (128 * 128 + 16384);  // 98304
    constexpr int SMEM2 = 3 * (64 * 128 + 16384);   // 73728
    cudaFuncSetAttribute(gemm1_plus_w2,
                         cudaFuncAttributeMaxDynamicSharedMemorySize, SMEM1);
    cudaFuncSetAttribute(gemm2_kernel,
                         cudaFuncAttributeMaxDynamicSharedMemorySize, SMEM2);

    // 1) prep + x convert + W1 convert
    convert_all_kernel<<<CONV_GRID, 256>>>(eid, x, W1, xv, w1);
    // 2) GEMM1 (M128xN128) with W2-convert blocks appended
    gemm1_plus_w2<<<G1_GRID, 256, SMEM1>>>(xv, w1, b1, av, W2, w2);
    // 3) GEMM2 (M64xN128)
    gemm2_kernel<<<dim3(P_OUT / 128, MAXT64), 256, SMEM2>>>(av, w2, b2, out);
}